// round 5
// baseline (speedup 1.0000x reference)
#include <cuda_runtime.h>

// ---------------------------------------------------------------------------
// InvertedResidual (ShuffleNetV2-style) fused pipeline, fp32 + packed f32x2.
//   K1: h1 = prelu(bn1(w2 @ x2))          (GEMM M=116,K=116,N=200704)
//   K2: h2 = bn2(dwconv3x3(h1))
//   K3: out_odd  = prelu(bn3(w3 @ h2))    (GEMM, interleaved write)
//       out_even = x1                     (copy, fused in K3 epilogue)
// ---------------------------------------------------------------------------

#define BFC   116
#define CINC  232
#define HWP   3136      // 56*56
#define NIMG  64
#define WPITCH 120      // padded k-pitch for weight smem (o-major)
#define NT    128       // N tile
#define KCH   4         // K chunk
#define NCHUNK 29       // 116 / 4

// scratch (allocation-free rule: __device__ globals)
__device__ float g_h1[NIMG * BFC * HWP];
__device__ float g_h2[NIMG * BFC * HWP];

// ---- packed f32x2 helpers -------------------------------------------------
__device__ __forceinline__ unsigned long long pk2(float x, float y) {
    unsigned long long r;
    asm("mov.b64 %0, {%1, %2};" : "=l"(r) : "f"(x), "f"(y));
    return r;
}
__device__ __forceinline__ void upk2(unsigned long long v, float& x, float& y) {
    asm("mov.b64 {%0, %1}, %2;" : "=f"(x), "=f"(y) : "l"(v));
}
__device__ __forceinline__ void fma2(unsigned long long& d,
                                     unsigned long long a,
                                     unsigned long long b) {
    asm("fma.rn.f32x2 %0, %1, %2, %3;" : "=l"(d) : "l"(a), "l"(b), "l"(d));
}

// ---------------------------------------------------------------------------
// Fused 1x1-conv GEMM + BN + PReLU.
// Tile: M=128 (116 real output channels, padded), N=128 spatial, K=116.
// 256 threads, each computes 8(M) x 8(N) split as {tr*4, 64+tr*4} x {tc*4, 64+tc*4}.
// Accumulators are f32x2 pairs over adjacent N.
// ---------------------------------------------------------------------------
template<bool FINAL>
__global__ __launch_bounds__(256, 2)
void gemm_fused(const float* __restrict__ x,
                const float* __restrict__ wmat,
                const float* __restrict__ bg, const float* __restrict__ bb,
                const float* __restrict__ bm, const float* __restrict__ bv,
                const float* __restrict__ alpha,
                float* __restrict__ out)
{
    extern __shared__ float smem[];
    float* ws = smem;                     // [128][WPITCH]  weights, o-major
    float* bs = smem + 128 * WPITCH;      // [2][KCH][NT]   input chunks

    const int tile = blockIdx.x;
    const int img  = blockIdx.y;
    const int n0   = tile * NT;
    const int tid  = (int)threadIdx.x;
    const int tr   = tid >> 4;            // 0..15  (M)
    const int tc   = tid & 15;            // 0..15  (N)

    const float* in = FINAL ? (g_h2 + img * (BFC * HWP))
                            : (x + img * (CINC * HWP) + BFC * HWP);

    // stage weights: coalesced global read (row-major [o][k]), o-major smem
    for (int i = tid; i < BFC * BFC; i += 256) {
        int o = i / BFC, k = i - o * BFC;
        ws[o * WPITCH + k] = wmat[i];
    }
    // zero the padded M rows (o = 116..127)
    for (int i = tid; i < (128 - BFC) * WPITCH; i += 256)
        ws[BFC * WPITCH + i] = 0.0f;

    // first B chunk: 4 k-rows x 128 n, one float2 per thread
    const int lr = tid >> 6;              // 0..3 (k row in chunk)
    const int lc = (tid & 63) * 2;        // 0..126 (n)
    const int gn = n0 + lc;
    const bool nok = gn < HWP;
    {
        float2 v = make_float2(0.f, 0.f);
        if (nok) v = *(const float2*)(in + lr * HWP + gn);
        *(float2*)(bs + lr * NT + lc) = v;
    }
    __syncthreads();

    unsigned long long acc[8][4];
    #pragma unroll
    for (int i = 0; i < 8; i++)
        #pragma unroll
        for (int j = 0; j < 4; j++) acc[i][j] = 0ULL;

    const int row0 = tr * 4;

    #pragma unroll 1
    for (int cc = 0; cc < NCHUNK; cc++) {
        // prefetch next chunk into registers (overlaps with compute)
        float2 nv = make_float2(0.f, 0.f);
        if (cc < NCHUNK - 1 && nok)
            nv = *(const float2*)(in + ((cc + 1) * KCH + lr) * HWP + gn);

        const float* bcur = bs + (cc & 1) * (KCH * NT);
        #pragma unroll
        for (int kc = 0; kc < KCH; kc++) {
            const int k = cc * KCH + kc;
            float4 b0 = *(const float4*)(bcur + kc * NT + tc * 4);
            float4 b1 = *(const float4*)(bcur + kc * NT + 64 + tc * 4);
            unsigned long long bp0 = pk2(b0.x, b0.y);
            unsigned long long bp1 = pk2(b0.z, b0.w);
            unsigned long long bp2 = pk2(b1.x, b1.y);
            unsigned long long bp3 = pk2(b1.z, b1.w);
            #pragma unroll
            for (int mi = 0; mi < 8; mi++) {
                const int row = (mi >> 2) * 64 + row0 + (mi & 3);
                float a = ws[row * WPITCH + k];
                unsigned long long ad = pk2(a, a);
                fma2(acc[mi][0], ad, bp0);
                fma2(acc[mi][1], ad, bp1);
                fma2(acc[mi][2], ad, bp2);
                fma2(acc[mi][3], ad, bp3);
            }
        }
        if (cc < NCHUNK - 1) {
            float* bnxt = bs + ((cc + 1) & 1) * (KCH * NT);
            *(float2*)(bnxt + lr * NT + lc) = nv;
            __syncthreads();
        }
    }

    // epilogue: BN + PReLU (+ interleave / x1 copy in FINAL)
    const float al = alpha[0];
    #pragma unroll
    for (int mi = 0; mi < 8; mi++) {
        const int o = (mi >> 2) * 64 + row0 + (mi & 3);
        if (o >= BFC) continue;
        const float s = bg[o] / sqrtf(bv[o] + 1e-5f);
        const float t = bb[o] - bm[o] * s;
        #pragma unroll
        for (int nh = 0; nh < 2; nh++) {
            const int n = n0 + nh * 64 + tc * 4;
            if (n >= HWP) continue;          // HWP % 64 == 0 -> half-tile granular
            float r[4];
            upk2(acc[mi][nh * 2 + 0], r[0], r[1]);
            upk2(acc[mi][nh * 2 + 1], r[2], r[3]);
            #pragma unroll
            for (int j = 0; j < 4; j++) {
                float v = r[j] * s + t;
                r[j] = (v >= 0.f) ? v : al * v;
            }
            if (FINAL) {
                // odd output channel 2o+1 = h[o]
                float* dsth = out + img * (CINC * HWP) + (2 * o + 1) * HWP + n;
                *(float4*)dsth = make_float4(r[0], r[1], r[2], r[3]);
                // even output channel 2o = x1[o]
                const float4 xv = *(const float4*)(x + img * (CINC * HWP) + o * HWP + n);
                float* dstx = out + img * (CINC * HWP) + (2 * o) * HWP + n;
                *(float4*)dstx = xv;
            } else {
                float* dst = g_h1 + img * (BFC * HWP) + o * HWP + n;
                *(float4*)dst = make_float4(r[0], r[1], r[2], r[3]);
            }
        }
    }
}

// ---------------------------------------------------------------------------
// Depthwise 3x3 (pad 1) + BN2. One CTA per (channel, image) 56x56 plane.
// ---------------------------------------------------------------------------
__global__ __launch_bounds__(256)
void dw_bn(const float* __restrict__ wdw,
           const float* __restrict__ bg, const float* __restrict__ bb,
           const float* __restrict__ bm, const float* __restrict__ bv)
{
    __shared__ float t[58 * 58];
    const int c   = blockIdx.x;
    const int img = blockIdx.y;
    const int tid = (int)threadIdx.x;

    for (int i = tid; i < 58 * 58; i += 256) t[i] = 0.0f;
    __syncthreads();

    const float* p = g_h1 + (img * BFC + c) * HWP;
    for (int i = tid; i < HWP; i += 256) {
        int y = i / 56, xx = i - y * 56;
        t[(y + 1) * 58 + (xx + 1)] = p[i];
    }
    __syncthreads();

    float w9[9];
    #pragma unroll
    for (int j = 0; j < 9; j++) w9[j] = wdw[c * 9 + j];
    const float s   = bg[c] / sqrtf(bv[c] + 1e-5f);
    const float off = bb[c] - bm[c] * s;

    float* q = g_h2 + (img * BFC + c) * HWP;
    for (int i = tid; i < HWP; i += 256) {
        int y = i / 56, xx = i - y * 56;
        const float* r = t + y * 58 + xx;
        float a = 0.f;
        #pragma unroll
        for (int dy = 0; dy < 3; dy++)
            #pragma unroll
            for (int dx = 0; dx < 3; dx++)
                a = fmaf(w9[dy * 3 + dx], r[dy * 58 + dx], a);
        q[i] = a * s + off;
    }
}

// ---------------------------------------------------------------------------
extern "C" void kernel_launch(void* const* d_in, const int* in_sizes, int n_in,
                              void* d_out, int out_size) {
    const float* x    = (const float*)d_in[0];
    const float* w2   = (const float*)d_in[1];
    const float* bn1g = (const float*)d_in[2];
    const float* bn1b = (const float*)d_in[3];
    const float* bn1m = (const float*)d_in[4];
    const float* bn1v = (const float*)d_in[5];
    const float* a1   = (const float*)d_in[6];
    const float* wdw  = (const float*)d_in[7];
    const float* bn2g = (const float*)d_in[8];
    const float* bn2b = (const float*)d_in[9];
    const float* bn2m = (const float*)d_in[10];
    const float* bn2v = (const float*)d_in[11];
    const float* w3   = (const float*)d_in[12];
    const float* bn3g = (const float*)d_in[13];
    const float* bn3b = (const float*)d_in[14];
    const float* bn3m = (const float*)d_in[15];
    const float* bn3v = (const float*)d_in[16];
    const float* a2   = (const float*)d_in[17];
    float* out = (float*)d_out;

    const int smem_gemm = (128 * WPITCH + 2 * KCH * NT) * (int)sizeof(float); // 65536
    cudaFuncSetAttribute(gemm_fused<false>,
                         cudaFuncAttributeMaxDynamicSharedMemorySize, smem_gemm);
    cudaFuncSetAttribute(gemm_fused<true>,
                         cudaFuncAttributeMaxDynamicSharedMemorySize, smem_gemm);

    dim3 gg(25, 64);   // ceil(3136/128) x batch
    gemm_fused<false><<<gg, 256, smem_gemm>>>(x, w2, bn1g, bn1b, bn1m, bn1v, a1, nullptr);
    dw_bn<<<dim3(116, 64), 256>>>(wdw, bn2g, bn2b, bn2m, bn2v);
    gemm_fused<true><<<gg, 256, smem_gemm>>>(x, w3, bn3g, bn3b, bn3m, bn3v, a2, out);
}

// round 7
// speedup vs baseline: 1.0013x; 1.0013x over previous
#include <cuda_runtime.h>

// ---------------------------------------------------------------------------
// InvertedResidual (ShuffleNetV2-style) fused pipeline, fp32 + packed f32x2.
//   K1: h1 = prelu(bn1(w2 @ x2))          (GEMM M=116,K=116,N=200704)
//   K2: h2 = bn2(dwconv3x3(h1))
//   K3: out_odd  = prelu(bn3(w3 @ h2))    (GEMM, interleaved write)
//       out_even = x1                     (copy, fused in K3 epilogue)
// ---------------------------------------------------------------------------

#define BFC   116
#define CINC  232
#define HWP   3136      // 56*56
#define NIMG  64
#define WPITCH 120      // padded k-pitch for weight smem (o-major)
#define NT    128       // N tile
#define KCH   4         // K chunk
#define NCHUNK 29       // 116 / 4

// scratch (allocation-free rule: __device__ globals)
__device__ float g_h1[NIMG * BFC * HWP];
__device__ float g_h2[NIMG * BFC * HWP];

// ---- packed f32x2 helpers -------------------------------------------------
__device__ __forceinline__ unsigned long long pk2(float x, float y) {
    unsigned long long r;
    asm("mov.b64 %0, {%1, %2};" : "=l"(r) : "f"(x), "f"(y));
    return r;
}
__device__ __forceinline__ void upk2(unsigned long long v, float& x, float& y) {
    asm("mov.b64 {%0, %1}, %2;" : "=f"(x), "=f"(y) : "l"(v));
}
__device__ __forceinline__ void fma2(unsigned long long& d,
                                     unsigned long long a,
                                     unsigned long long b) {
    asm("fma.rn.f32x2 %0, %1, %2, %3;" : "=l"(d) : "l"(a), "l"(b), "l"(d));
}

// ---------------------------------------------------------------------------
// Fused 1x1-conv GEMM + BN + PReLU.
// Tile: M=128 (116 real output channels, padded), N=128 spatial, K=116.
// 256 threads, each computes 8(M) x 8(N) split as {tr*4, 64+tr*4} x {tc*4, 64+tc*4}.
// Accumulators are f32x2 pairs over adjacent N.
// ---------------------------------------------------------------------------
template<bool FINAL>
__global__ __launch_bounds__(256, 2)
void gemm_fused(const float* __restrict__ x,
                const float* __restrict__ wmat,
                const float* __restrict__ bg, const float* __restrict__ bb,
                const float* __restrict__ bm, const float* __restrict__ bv,
                const float* __restrict__ alpha,
                float* __restrict__ out)
{
    extern __shared__ float smem[];
    float* ws = smem;                     // [128][WPITCH]  weights, o-major
    float* bs = smem + 128 * WPITCH;      // [2][KCH][NT]   input chunks

    const int tile = blockIdx.x;
    const int img  = blockIdx.y;
    const int n0   = tile * NT;
    const int tid  = (int)threadIdx.x;
    const int tr   = tid >> 4;            // 0..15  (M)
    const int tc   = tid & 15;            // 0..15  (N)

    const float* in = FINAL ? (g_h2 + img * (BFC * HWP))
                            : (x + img * (CINC * HWP) + BFC * HWP);

    // stage weights: coalesced global read (row-major [o][k]), o-major smem
    for (int i = tid; i < BFC * BFC; i += 256) {
        int o = i / BFC, k = i - o * BFC;
        ws[o * WPITCH + k] = wmat[i];
    }
    // zero the padded M rows (o = 116..127)
    for (int i = tid; i < (128 - BFC) * WPITCH; i += 256)
        ws[BFC * WPITCH + i] = 0.0f;

    // first B chunk: 4 k-rows x 128 n, one float2 per thread
    const int lr = tid >> 6;              // 0..3 (k row in chunk)
    const int lc = (tid & 63) * 2;        // 0..126 (n)
    const int gn = n0 + lc;
    const bool nok = gn < HWP;
    {
        float2 v = make_float2(0.f, 0.f);
        if (nok) v = *(const float2*)(in + lr * HWP + gn);
        *(float2*)(bs + lr * NT + lc) = v;
    }
    __syncthreads();

    unsigned long long acc[8][4];
    #pragma unroll
    for (int i = 0; i < 8; i++)
        #pragma unroll
        for (int j = 0; j < 4; j++) acc[i][j] = 0ULL;

    const int row0 = tr * 4;

    #pragma unroll 1
    for (int cc = 0; cc < NCHUNK; cc++) {
        // prefetch next chunk into registers (overlaps with compute)
        float2 nv = make_float2(0.f, 0.f);
        if (cc < NCHUNK - 1 && nok)
            nv = *(const float2*)(in + ((cc + 1) * KCH + lr) * HWP + gn);

        const float* bcur = bs + (cc & 1) * (KCH * NT);
        #pragma unroll
        for (int kc = 0; kc < KCH; kc++) {
            const int k = cc * KCH + kc;
            float4 b0 = *(const float4*)(bcur + kc * NT + tc * 4);
            float4 b1 = *(const float4*)(bcur + kc * NT + 64 + tc * 4);
            unsigned long long bp0 = pk2(b0.x, b0.y);
            unsigned long long bp1 = pk2(b0.z, b0.w);
            unsigned long long bp2 = pk2(b1.x, b1.y);
            unsigned long long bp3 = pk2(b1.z, b1.w);
            #pragma unroll
            for (int mi = 0; mi < 8; mi++) {
                const int row = (mi >> 2) * 64 + row0 + (mi & 3);
                float a = ws[row * WPITCH + k];
                unsigned long long ad = pk2(a, a);
                fma2(acc[mi][0], ad, bp0);
                fma2(acc[mi][1], ad, bp1);
                fma2(acc[mi][2], ad, bp2);
                fma2(acc[mi][3], ad, bp3);
            }
        }
        if (cc < NCHUNK - 1) {
            float* bnxt = bs + ((cc + 1) & 1) * (KCH * NT);
            *(float2*)(bnxt + lr * NT + lc) = nv;
            __syncthreads();
        }
    }

    // epilogue: BN + PReLU (+ interleave / x1 copy in FINAL)
    const float al = alpha[0];
    #pragma unroll
    for (int mi = 0; mi < 8; mi++) {
        const int o = (mi >> 2) * 64 + row0 + (mi & 3);
        if (o >= BFC) continue;
        const float s = bg[o] / sqrtf(bv[o] + 1e-5f);
        const float t = bb[o] - bm[o] * s;
        #pragma unroll
        for (int nh = 0; nh < 2; nh++) {
            const int n = n0 + nh * 64 + tc * 4;
            if (n >= HWP) continue;          // HWP % 64 == 0 -> half-tile granular
            float r[4];
            upk2(acc[mi][nh * 2 + 0], r[0], r[1]);
            upk2(acc[mi][nh * 2 + 1], r[2], r[3]);
            #pragma unroll
            for (int j = 0; j < 4; j++) {
                float v = r[j] * s + t;
                r[j] = (v >= 0.f) ? v : al * v;
            }
            if (FINAL) {
                // odd output channel 2o+1 = h[o]
                float* dsth = out + img * (CINC * HWP) + (2 * o + 1) * HWP + n;
                *(float4*)dsth = make_float4(r[0], r[1], r[2], r[3]);
                // even output channel 2o = x1[o]
                const float4 xv = *(const float4*)(x + img * (CINC * HWP) + o * HWP + n);
                float* dstx = out + img * (CINC * HWP) + (2 * o) * HWP + n;
                *(float4*)dstx = xv;
            } else {
                float* dst = g_h1 + img * (BFC * HWP) + o * HWP + n;
                *(float4*)dst = make_float4(r[0], r[1], r[2], r[3]);
            }
        }
    }
}

// ---------------------------------------------------------------------------
// Depthwise 3x3 (pad 1) + BN2. One CTA per (channel, image) 56x56 plane.
// ---------------------------------------------------------------------------
__global__ __launch_bounds__(256)
void dw_bn(const float* __restrict__ wdw,
           const float* __restrict__ bg, const float* __restrict__ bb,
           const float* __restrict__ bm, const float* __restrict__ bv)
{
    __shared__ float t[58 * 58];
    const int c   = blockIdx.x;
    const int img = blockIdx.y;
    const int tid = (int)threadIdx.x;

    for (int i = tid; i < 58 * 58; i += 256) t[i] = 0.0f;
    __syncthreads();

    const float* p = g_h1 + (img * BFC + c) * HWP;
    for (int i = tid; i < HWP; i += 256) {
        int y = i / 56, xx = i - y * 56;
        t[(y + 1) * 58 + (xx + 1)] = p[i];
    }
    __syncthreads();

    float w9[9];
    #pragma unroll
    for (int j = 0; j < 9; j++) w9[j] = wdw[c * 9 + j];
    const float s   = bg[c] / sqrtf(bv[c] + 1e-5f);
    const float off = bb[c] - bm[c] * s;

    float* q = g_h2 + (img * BFC + c) * HWP;
    for (int i = tid; i < HWP; i += 256) {
        int y = i / 56, xx = i - y * 56;
        const float* r = t + y * 58 + xx;
        float a = 0.f;
        #pragma unroll
        for (int dy = 0; dy < 3; dy++)
            #pragma unroll
            for (int dx = 0; dx < 3; dx++)
                a = fmaf(w9[dy * 3 + dx], r[dy * 58 + dx], a);
        q[i] = a * s + off;
    }
}

// ---------------------------------------------------------------------------
extern "C" void kernel_launch(void* const* d_in, const int* in_sizes, int n_in,
                              void* d_out, int out_size) {
    const float* x    = (const float*)d_in[0];
    const float* w2   = (const float*)d_in[1];
    const float* bn1g = (const float*)d_in[2];
    const float* bn1b = (const float*)d_in[3];
    const float* bn1m = (const float*)d_in[4];
    const float* bn1v = (const float*)d_in[5];
    const float* a1   = (const float*)d_in[6];
    const float* wdw  = (const float*)d_in[7];
    const float* bn2g = (const float*)d_in[8];
    const float* bn2b = (const float*)d_in[9];
    const float* bn2m = (const float*)d_in[10];
    const float* bn2v = (const float*)d_in[11];
    const float* w3   = (const float*)d_in[12];
    const float* bn3g = (const float*)d_in[13];
    const float* bn3b = (const float*)d_in[14];
    const float* bn3m = (const float*)d_in[15];
    const float* bn3v = (const float*)d_in[16];
    const float* a2   = (const float*)d_in[17];
    float* out = (float*)d_out;

    const int smem_gemm = (128 * WPITCH + 2 * KCH * NT) * (int)sizeof(float); // 65536
    cudaFuncSetAttribute(gemm_fused<false>,
                         cudaFuncAttributeMaxDynamicSharedMemorySize, smem_gemm);
    cudaFuncSetAttribute(gemm_fused<true>,
                         cudaFuncAttributeMaxDynamicSharedMemorySize, smem_gemm);

    dim3 gg(25, 64);   // ceil(3136/128) x batch
    gemm_fused<false><<<gg, 256, smem_gemm>>>(x, w2, bn1g, bn1b, bn1m, bn1v, a1, nullptr);
    dw_bn<<<dim3(116, 64), 256>>>(wdw, bn2g, bn2b, bn2m, bn2v);
    gemm_fused<true><<<gg, 256, smem_gemm>>>(x, w3, bn3g, bn3b, bn3m, bn3v, a2, out);
}

// round 11
// speedup vs baseline: 1.0556x; 1.0542x over previous
#include <cuda_runtime.h>
#include <cuda_bf16.h>
#include <cstdint>

#define BFC 116
#define CINC 232
#define HWP 3136
#define NIMG 64
#define PITCH 136          // bf16 elems per smem row (68 words; 68 % 32 == 4)

// smem byte offsets
#define A_OFF  0           // A hi [128][136] then A lo  (69632 B total)
#define AL_OFF 34816
#define BH_OFF 69632       // B hi [128][136]
#define BL_OFF 104448      // B lo
#define BN_OFF 139264      // s[128] floats, t[128] floats
#define SMT    140800

// scratch (allocation-free rule: __device__ globals)
__device__ __align__(16) float g_h1[(size_t)NIMG * BFC * HWP];
__device__ __align__(16) float g_h2[(size_t)NIMG * BFC * HWP];
// pre-split weights, exact smem A image: [mat][hilo][128*136] bf16
__device__ __align__(16) __nv_bfloat16 g_wA[2][2][128 * PITCH];

// ---------------- PTX helpers ----------------------------------------------
__device__ __forceinline__ uint32_t smem_u32(const void* p) {
    uint32_t a;
    asm("{ .reg .u64 t; cvta.to.shared.u64 t, %1; cvt.u32.u64 %0, t; }" : "=r"(a) : "l"(p));
    return a;
}
__device__ __forceinline__ void ldsm4(uint32_t* r, uint32_t addr) {
    asm volatile("ldmatrix.sync.aligned.m8n8.x4.shared.b16 {%0,%1,%2,%3}, [%4];"
                 : "=r"(r[0]), "=r"(r[1]), "=r"(r[2]), "=r"(r[3]) : "r"(addr));
}
__device__ __forceinline__ void mma_bf16(float* d, const uint32_t* a, const uint32_t* b) {
    asm volatile(
        "mma.sync.aligned.m16n8k16.row.col.f32.bf16.bf16.f32 "
        "{%0,%1,%2,%3}, {%4,%5,%6,%7}, {%8,%9}, {%0,%1,%2,%3};"
        : "+f"(d[0]), "+f"(d[1]), "+f"(d[2]), "+f"(d[3])
        : "r"(a[0]), "r"(a[1]), "r"(a[2]), "r"(a[3]), "r"(b[0]), "r"(b[1]));
}
__device__ __forceinline__ void split_bf16(float v, unsigned short& h, unsigned short& l) {
    __nv_bfloat16 hb = __float2bfloat16(v);
    __nv_bfloat16 lb = __float2bfloat16(v - __bfloat162float(hb));
    h = *(unsigned short*)&hb;
    l = *(unsigned short*)&lb;
}

// ---------------------------------------------------------------------------
// Weight prep: fp32 [116x116] -> padded [128][136] bf16 hi/lo smem image.
// ---------------------------------------------------------------------------
__global__ void prep_w(const float* __restrict__ w2, const float* __restrict__ w3) {
    int i = blockIdx.x * blockDim.x + threadIdx.x;
    if (i >= 2 * 128 * PITCH) return;
    const int mat = i / (128 * PITCH);
    const int r = i % (128 * PITCH);
    const int m = r / PITCH, k = r % PITCH;
    const float* w = mat ? w3 : w2;
    float v = (m < BFC && k < BFC) ? w[m * BFC + k] : 0.f;
    unsigned short h, l;
    split_bf16(v, h, l);
    ((unsigned short*)&g_wA[mat][0][0])[r] = h;
    ((unsigned short*)&g_wA[mat][1][0])[r] = l;
}

// ---------------------------------------------------------------------------
// Fused 1x1-conv GEMM (mma.sync bf16-split, fp32 accum) + BN + PReLU.
// CTA: M=128 x N=128 x K=128(pad). 8 warps in 2(M) x 4(N).
// ---------------------------------------------------------------------------
template<bool FINAL>
__global__ __launch_bounds__(256, 1)
void gemm_mma(const float* __restrict__ x,
              const float* __restrict__ bg, const float* __restrict__ bb,
              const float* __restrict__ bm, const float* __restrict__ bv,
              const float* __restrict__ alpha,
              float* __restrict__ out) {
    extern __shared__ char smem[];
    const uint32_t sb = smem_u32(smem);
    const int tid = (int)threadIdx.x, wid = tid >> 5, lane = tid & 31;
    const int img = blockIdx.y;
    const int n0 = blockIdx.x * 128;

    // ---- stage A: raw copy of pre-split weight image (hi+lo, 69632 B) ----
    {
        const uint4* s = (const uint4*)&g_wA[FINAL ? 1 : 0][0][0];
        uint4* d = (uint4*)(smem + A_OFF);
        #pragma unroll 4
        for (int i = tid; i < 4352; i += 256) d[i] = s[i];
    }

    // ---- stage B: transpose fp32 [k][HWP] -> bf16 hi/lo [n][PITCH] ----
    const float* in = FINAL ? (g_h2 + (size_t)img * BFC * HWP)
                            : (x + (size_t)img * CINC * HWP + (size_t)BFC * HWP);
    uint32_t* bhw = (uint32_t*)(smem + BH_OFF);
    uint32_t* blw = (uint32_t*)(smem + BL_OFF);
    #pragma unroll 4
    for (int it = 0; it < 32; it++) {
        const int flat = it * 256 + tid;     // 0..8191
        const int kp = flat >> 7;            // k-pair 0..63
        const int n = flat & 127;
        const int k0 = kp * 2;
        const bool nok = (n0 + n) < HWP;
        float v0 = (nok && k0 < BFC)     ? in[(size_t)k0 * HWP + n0 + n] : 0.f;
        float v1 = (nok && k0 + 1 < BFC) ? in[(size_t)(k0 + 1) * HWP + n0 + n] : 0.f;
        unsigned short h0, l0, h1, l1;
        split_bf16(v0, h0, l0);
        split_bf16(v1, h1, l1);
        bhw[n * 68 + kp] = (uint32_t)h0 | ((uint32_t)h1 << 16);
        blw[n * 68 + kp] = (uint32_t)l0 | ((uint32_t)l1 << 16);
    }

    // ---- BN coefficients -> smem ----
    float* sS = (float*)(smem + BN_OFF);
    float* sT = sS + 128;
    if (tid < 128) {
        float s = 0.f, t = 0.f;
        if (tid < BFC) {
            s = bg[tid] * rsqrtf(bv[tid] + 1e-5f);
            t = bb[tid] - bm[tid] * s;
        }
        sS[tid] = s;
        sT[tid] = t;
    }
    __syncthreads();

    // ---- MMA mainloop ----
    const int mw = (wid & 1) * 64;
    const int nw = (wid >> 1) * 32;
    float acc[4][4][4];
    #pragma unroll
    for (int a = 0; a < 4; a++)
        #pragma unroll
        for (int b = 0; b < 4; b++)
            #pragma unroll
            for (int c = 0; c < 4; c++) acc[a][b][c] = 0.f;

    const int lrow = lane & 15;
    const int lkh = (lane >> 4) << 4;    // 0 or 16 bytes (k-half)

    #pragma unroll 1
    for (int ks = 0; ks < 8; ks++) {
        const int kb = ks * 32;          // k byte offset (16 elems * 2B)
        uint32_t Ah[4][4], Al[4][4], Bh[4][2], Bl[4][2];
        #pragma unroll
        for (int mf = 0; mf < 4; mf++) {
            const uint32_t rowoff = (uint32_t)((mw + mf * 16 + lrow) * (PITCH * 2)) + kb + lkh;
            ldsm4(Ah[mf], sb + A_OFF + rowoff);
            ldsm4(Al[mf], sb + AL_OFF + rowoff);
        }
        #pragma unroll
        for (int bg2 = 0; bg2 < 2; bg2++) {
            const uint32_t rowoff = (uint32_t)((nw + bg2 * 16 + lrow) * (PITCH * 2)) + kb + lkh;
            uint32_t t[4];
            ldsm4(t, sb + BH_OFF + rowoff);
            Bh[bg2 * 2 + 0][0] = t[0]; Bh[bg2 * 2 + 0][1] = t[2];
            Bh[bg2 * 2 + 1][0] = t[1]; Bh[bg2 * 2 + 1][1] = t[3];
            ldsm4(t, sb + BL_OFF + rowoff);
            Bl[bg2 * 2 + 0][0] = t[0]; Bl[bg2 * 2 + 0][1] = t[2];
            Bl[bg2 * 2 + 1][0] = t[1]; Bl[bg2 * 2 + 1][1] = t[3];
        }
        #pragma unroll
        for (int mf = 0; mf < 4; mf++)
            #pragma unroll
            for (int nf = 0; nf < 4; nf++) {
                mma_bf16(acc[mf][nf], Ah[mf], Bh[nf]);
                mma_bf16(acc[mf][nf], Ah[mf], Bl[nf]);
                mma_bf16(acc[mf][nf], Al[mf], Bh[nf]);
            }
    }

    // ---- epilogue: BN + PReLU + store (+ shuffle interleave / x1 copy) ----
    const float al = alpha[0];
    const int r = lane >> 2;
    const int c2 = (lane & 3) * 2;
    #pragma unroll
    for (int mf = 0; mf < 4; mf++) {
        const int o0 = mw + mf * 16 + r;
        const int o1 = o0 + 8;
        const float s0 = sS[o0], t0 = sT[o0];
        const float s1 = sS[o1], t1 = sT[o1];
        #pragma unroll
        for (int nf = 0; nf < 4; nf++) {
            const int n = n0 + nw + nf * 8 + c2;
            if (n >= HWP) continue;
            float2 vA, vB;
            vA.x = acc[mf][nf][0] * s0 + t0;
            vA.y = acc[mf][nf][1] * s0 + t0;
            vB.x = acc[mf][nf][2] * s1 + t1;
            vB.y = acc[mf][nf][3] * s1 + t1;
            vA.x = vA.x >= 0.f ? vA.x : al * vA.x;
            vA.y = vA.y >= 0.f ? vA.y : al * vA.y;
            vB.x = vB.x >= 0.f ? vB.x : al * vB.x;
            vB.y = vB.y >= 0.f ? vB.y : al * vB.y;
            if (FINAL) {
                float* ob = out + (size_t)img * CINC * HWP;
                const float* xb = x + (size_t)img * CINC * HWP;
                if (o0 < BFC) {
                    *(float2*)(ob + (size_t)(2 * o0 + 1) * HWP + n) = vA;
                    *(float2*)(ob + (size_t)(2 * o0) * HWP + n) =
                        *(const float2*)(xb + (size_t)o0 * HWP + n);
                }
                if (o1 < BFC) {
                    *(float2*)(ob + (size_t)(2 * o1 + 1) * HWP + n) = vB;
                    *(float2*)(ob + (size_t)(2 * o1) * HWP + n) =
                        *(const float2*)(xb + (size_t)o1 * HWP + n);
                }
            } else {
                float* hb = g_h1 + (size_t)img * BFC * HWP;
                if (o0 < BFC) *(float2*)(hb + (size_t)o0 * HWP + n) = vA;
                if (o1 < BFC) *(float2*)(hb + (size_t)o1 * HWP + n) = vB;
            }
        }
    }
}

// ---------------------------------------------------------------------------
// Depthwise 3x3 (pad 1) + BN2. Block (56,4): column strips, no divides.
// ---------------------------------------------------------------------------
__global__ __launch_bounds__(224)
void dw_bn(const float* __restrict__ wdw,
           const float* __restrict__ bg, const float* __restrict__ bb,
           const float* __restrict__ bm, const float* __restrict__ bv)
{
    __shared__ float t[58 * 58];
    const int c = blockIdx.x, img = blockIdx.y;
    const int tx = (int)threadIdx.x, ty = (int)threadIdx.y;
    const int tid = ty * 56 + tx;

    for (int i = tid; i < 58 * 58; i += 224) t[i] = 0.0f;
    __syncthreads();

    const float* p = g_h1 + ((size_t)img * BFC + c) * HWP;
    for (int i = tid; i < HWP; i += 224) {
        int y = i / 56, xx = i - y * 56;
        t[(y + 1) * 58 + (xx + 1)] = p[i];
    }
    __syncthreads();

    float w9[9];
    #pragma unroll
    for (int j = 0; j < 9; j++) w9[j] = wdw[c * 9 + j];
    const float s = bg[c] * rsqrtf(bv[c] + 1e-5f);
    const float off = bb[c] - bm[c] * s;

    float* q = g_h2 + ((size_t)img * BFC + c) * HWP;
    #pragma unroll
    for (int y = ty; y < 56; y += 4) {
        const float* r = t + y * 58 + tx;
        float a = 0.f;
        #pragma unroll
        for (int dy = 0; dy < 3; dy++)
            #pragma unroll
            for (int dx = 0; dx < 3; dx++)
                a = fmaf(w9[dy * 3 + dx], r[dy * 58 + dx], a);
        q[y * 56 + tx] = a * s + off;
    }
}

// ---------------------------------------------------------------------------
extern "C" void kernel_launch(void* const* d_in, const int* in_sizes, int n_in,
                              void* d_out, int out_size) {
    const float* x    = (const float*)d_in[0];
    const float* w2   = (const float*)d_in[1];
    const float* bn1g = (const float*)d_in[2];
    const float* bn1b = (const float*)d_in[3];
    const float* bn1m = (const float*)d_in[4];
    const float* bn1v = (const float*)d_in[5];
    const float* a1   = (const float*)d_in[6];
    const float* wdw  = (const float*)d_in[7];
    const float* bn2g = (const float*)d_in[8];
    const float* bn2b = (const float*)d_in[9];
    const float* bn2m = (const float*)d_in[10];
    const float* bn2v = (const float*)d_in[11];
    const float* w3   = (const float*)d_in[12];
    const float* bn3g = (const float*)d_in[13];
    const float* bn3b = (const float*)d_in[14];
    const float* bn3m = (const float*)d_in[15];
    const float* bn3v = (const float*)d_in[16];
    const float* a2   = (const float*)d_in[17];
    float* out = (float*)d_out;

    cudaFuncSetAttribute(gemm_mma<false>, cudaFuncAttributeMaxDynamicSharedMemorySize, SMT);
    cudaFuncSetAttribute(gemm_mma<true>,  cudaFuncAttributeMaxDynamicSharedMemorySize, SMT);

    prep_w<<<(2 * 128 * PITCH + 511) / 512, 512>>>(w2, w3);
    dim3 gg(25, 64);
    gemm_mma<false><<<gg, 256, SMT>>>(x, bn1g, bn1b, bn1m, bn1v, a1, nullptr);
    dw_bn<<<dim3(116, 64), dim3(56, 4)>>>(wdw, bn2g, bn2b, bn2m, bn2v);
    gemm_mma<true><<<gg, 256, SMT>>>(x, bn3g, bn3b, bn3m, bn3v, a2, out);
}